// round 3
// baseline (speedup 1.0000x reference)
#include <cuda_runtime.h>
#include <math.h>
#include <stdint.h>

// RoPE: X (L=2048, D=4096, N=4) fp32, row-major.
// out[:, :half]  = cos*x1 - sin*x2 ; out[:, half:] = sin*x1 + cos*x2
// theta_i = 10000^(i/2048), ang = (l+1)*theta_i  (fp32 in the reference)
//
// Single kernel. theta rebuilt per-thread as a double-float product of
// host-computed constants c_k = 10000^(2^k/2048) over the bits of i.
// Streaming cache hints (__ldcs/__stcs): data is touched exactly once.

#define L_DIM 2048
#define D4    4096      // float4s per l-row (D floats / N=4 floats per float4)
#define HALF  2048
#define G     4         // l-values per thread

struct ThetaC { float hi[11]; float lo[11]; };

__global__ __launch_bounds__(256)
void rope_kernel(const float4* __restrict__ X, float4* __restrict__ out, ThetaC tc) {
    int t  = blockIdx.x * blockDim.x + threadIdx.x;   // 0 .. (L/G)*HALF - 1
    int i  = t & (HALF - 1);                          // rotary index
    int l0 = (t >> 11) * G;                           // first l for this thread

    // ---- front-batched streaming loads (evict-first) -------------------
    int base = l0 * D4 + i;
    float4 x1[G], x2[G];
    #pragma unroll
    for (int k = 0; k < G; k++) {
        x1[k] = __ldcs(&X[base + k * D4]);
        x2[k] = __ldcs(&X[base + k * D4 + HALF]);
    }

    // ---- double-float theta = prod_{bit k of i} c_k --------------------
    float th = 1.0f, tl = 0.0f;
    #pragma unroll
    for (int k = 0; k < 11; k++) {
        if (i & (1 << k)) {
            float bh = tc.hi[k], bl = tc.lo[k];
            float p  = th * bh;
            float e  = fmaf(th, bh, -p);
            e        = fmaf(th, bl, e);
            e        = fmaf(tl, bh, e);
            float s  = p + e;
            tl       = (p - s) + e;
            th       = s;
        }
    }
    float theta = th + tl;   // correctly-rounded fp32 theta

    // ---- rotate + streaming stores --------------------------------------
    #pragma unroll
    for (int k = 0; k < G; k++) {
        // exactly one fp32 multiply, as in the reference
        float ang = (float)(l0 + k + 1) * theta;

        // exact-angle range reduction in double (|ang| < 2.1e7 << 2^53)
        double ad = (double)ang;
        double q  = rint(ad * 0.15915494309189535);          // 1/(2*pi)
        float  r  = (float)fma(q, -6.283185307179586, ad);

        float s, c;
        sincosf(r, &s, &c);   // |r| <= pi: fast polynomial path

        float4 a = x1[k], b = x2[k], o1, o2;
        o1.x = c * a.x - s * b.x;  o1.y = c * a.y - s * b.y;
        o1.z = c * a.z - s * b.z;  o1.w = c * a.w - s * b.w;
        o2.x = s * a.x + c * b.x;  o2.y = s * a.y + c * b.y;
        o2.z = s * a.z + c * b.z;  o2.w = s * a.w + c * b.w;

        __stcs(&out[base + k * D4],        o1);
        __stcs(&out[base + k * D4 + HALF], o2);
    }
}

extern "C" void kernel_launch(void* const* d_in, const int* in_sizes, int n_in,
                              void* d_out, int out_size) {
    const float4* X   = (const float4*)d_in[0];
    float4*       out = (float4*)d_out;

    ThetaC tc;
    for (int k = 0; k < 11; k++) {
        double c = pow(10000.0, (double)(1 << k) / 2048.0);
        tc.hi[k] = (float)c;
        tc.lo[k] = (float)(c - (double)tc.hi[k]);
    }

    int total = (L_DIM / G) * HALF;           // 1,048,576 threads
    rope_kernel<<<total / 256, 256>>>(X, out, tc);
}